// round 1
// baseline (speedup 1.0000x reference)
#include <cuda_runtime.h>
#include <math.h>

// Problem constants
#define D_EMB   1024
#define SEQ_T   2048
#define BATCH   2
#define NHEAD   16
#define DK      64
#define M_TOT   (BATCH * SEQ_T)      // 4096 rows for the projection GEMMs

// Scratch (device globals: allocation-free rule)
__device__ float g_Q[(size_t)BATCH * NHEAD * SEQ_T * DK];   // [B,H,T,Dk]
__device__ float g_K[(size_t)BATCH * NHEAD * SEQ_T * DK];
__device__ float g_V[(size_t)BATCH * NHEAD * SEQ_T * DK];
__device__ float g_A[(size_t)M_TOT * D_EMB];                // attention output, [B,T,H*Dk]

// ---------------------------------------------------------------------------
// GEMM: C = A[M,1024] * W[1024,1024], 64x64 block tile, 256 threads, 4x4 micro
// MODE 0: QKV projection — W/dst chosen by blockIdx.z, epilogue remaps heads
// MODE 1: output projection — plain row-major store
// ---------------------------------------------------------------------------
template <int MODE>
__global__ void mha_gemm_kernel(const float* __restrict__ A,
                                const float* __restrict__ W0,
                                const float* __restrict__ W1,
                                const float* __restrict__ W2,
                                float* __restrict__ Cout) {
    const float* W;
    float* dst;
    if (MODE == 0) {
        if (blockIdx.z == 0)      { W = W0; dst = g_Q; }
        else if (blockIdx.z == 1) { W = W1; dst = g_K; }
        else                      { W = W2; dst = g_V; }
    } else {
        W = W0; dst = Cout;
    }

    __shared__ float As[16][65];   // As[k][m], padded
    __shared__ float Bs[16][68];   // Bs[k][n], padded to keep float4 alignment

    const int tid = threadIdx.x;
    const int tx = tid & 15;
    const int ty = tid >> 4;
    const int m0 = blockIdx.y << 6;
    const int n0 = blockIdx.x << 6;

    const int a_row = tid >> 2;          // 0..63
    const int a_col = (tid & 3) << 2;    // 0,4,8,12
    const int b_row = tid >> 4;          // 0..15
    const int b_col = (tid & 15) << 2;   // 0..60

    float acc[4][4];
#pragma unroll
    for (int i = 0; i < 4; i++)
#pragma unroll
        for (int j = 0; j < 4; j++) acc[i][j] = 0.0f;

    const float* Ag = A + (size_t)(m0 + a_row) * D_EMB + a_col;
    const float* Bg = W + (size_t)b_row * D_EMB + n0 + b_col;

    for (int k0 = 0; k0 < D_EMB; k0 += 16) {
        float4 av = *(const float4*)(Ag + k0);
        float4 bv = *(const float4*)(Bg + (size_t)k0 * D_EMB);
        As[a_col + 0][a_row] = av.x;
        As[a_col + 1][a_row] = av.y;
        As[a_col + 2][a_row] = av.z;
        As[a_col + 3][a_row] = av.w;
        *(float4*)&Bs[b_row][b_col] = bv;
        __syncthreads();

#pragma unroll
        for (int k = 0; k < 16; k++) {
            float4 rb = *(const float4*)&Bs[k][tx << 2];
            float ra0 = As[k][(ty << 2) + 0];
            float ra1 = As[k][(ty << 2) + 1];
            float ra2 = As[k][(ty << 2) + 2];
            float ra3 = As[k][(ty << 2) + 3];
            acc[0][0] += ra0 * rb.x; acc[0][1] += ra0 * rb.y; acc[0][2] += ra0 * rb.z; acc[0][3] += ra0 * rb.w;
            acc[1][0] += ra1 * rb.x; acc[1][1] += ra1 * rb.y; acc[1][2] += ra1 * rb.z; acc[1][3] += ra1 * rb.w;
            acc[2][0] += ra2 * rb.x; acc[2][1] += ra2 * rb.y; acc[2][2] += ra2 * rb.z; acc[2][3] += ra2 * rb.w;
            acc[3][0] += ra3 * rb.x; acc[3][1] += ra3 * rb.y; acc[3][2] += ra3 * rb.z; acc[3][3] += ra3 * rb.w;
        }
        __syncthreads();
    }

    if (MODE == 0) {
        // remap (m = b*T + t, n = h*64 + d) -> dst[((b*H + h)*T + t)*64 + d]
#pragma unroll
        for (int i = 0; i < 4; i++) {
            int m = m0 + (ty << 2) + i;
            int b = m >> 11;            // /2048
            int t = m & 2047;
#pragma unroll
            for (int j = 0; j < 4; j++) {
                int n = n0 + (tx << 2) + j;
                int h = n >> 6;
                int d = n & 63;
                dst[((size_t)((b << 4) + h) * SEQ_T + t) * DK + d] = acc[i][j];
            }
        }
    } else {
#pragma unroll
        for (int i = 0; i < 4; i++) {
            int m = m0 + (ty << 2) + i;
            float* crow = dst + (size_t)m * D_EMB + n0 + (tx << 2);
#pragma unroll
            for (int j = 0; j < 4; j++) crow[j] = acc[i][j];
        }
    }
}

// ---------------------------------------------------------------------------
// Causal flash attention, fp32.
// Grid: (T/64 q-tiles, B*H). Block: 256 threads (16x16, 4x4 microtile).
// smem: Qs[64][64] + KPs[64][64] (K^T, reused for P) + Vs[64][64] = 48 KB.
// ---------------------------------------------------------------------------
__global__ void mha_attn_kernel() {
    __shared__ float Qs[64 * 64];
    __shared__ float KPs[64 * 64];   // K stored transposed [d][c]; reused as P [r][c]
    __shared__ float Vs[64 * 64];

    const int tid = threadIdx.x;
    const int tx = tid & 15;
    const int ty = tid >> 4;
    const int qt = blockIdx.x;           // q tile, 0..31
    const int bh = blockIdx.y;           // 0..31

    const float* Qg = g_Q + (size_t)bh * (SEQ_T * DK) + (size_t)qt * 64 * DK;
    const float* Kg = g_K + (size_t)bh * (SEQ_T * DK);
    const float* Vg = g_V + (size_t)bh * (SEQ_T * DK);

    // Load Q tile once, pre-scaled by 1/sqrt(Dk) = 0.125
    for (int e = tid; e < 64 * 16; e += 256) {
        int r = e >> 4;
        int c4 = (e & 15) << 2;
        float4 v = *(const float4*)&Qg[r * DK + c4];
        v.x *= 0.125f; v.y *= 0.125f; v.z *= 0.125f; v.w *= 0.125f;
        *(float4*)&Qs[r * 64 + c4] = v;
    }

    float m_i[4], l_i[4], o[4][4];
#pragma unroll
    for (int i = 0; i < 4; i++) {
        m_i[i] = -1e30f;
        l_i[i] = 0.0f;
#pragma unroll
        for (int j = 0; j < 4; j++) o[i][j] = 0.0f;
    }

    for (int j0 = 0; j0 <= qt; j0++) {
        __syncthreads();   // prev PV / Q-load visibility before overwriting tiles

        // Load K transposed (row-fast mapping => conflict-free transposed stores)
        for (int e = tid; e < 64 * 16; e += 256) {
            int r = e & 63;            // kv row within tile
            int c4 = (e >> 6) << 2;    // d chunk
            float4 kv = *(const float4*)&Kg[(size_t)(j0 * 64 + r) * DK + c4];
            KPs[(c4 + 0) * 64 + r] = kv.x;
            KPs[(c4 + 1) * 64 + r] = kv.y;
            KPs[(c4 + 2) * 64 + r] = kv.z;
            KPs[(c4 + 3) * 64 + r] = kv.w;
        }
        // Load V straight (coalesced)
        for (int e = tid; e < 64 * 16; e += 256) {
            int r = e >> 4;
            int c4 = (e & 15) << 2;
            *(float4*)&Vs[r * 64 + c4] = *(const float4*)&Vg[(size_t)(j0 * 64 + r) * DK + c4];
        }
        __syncthreads();

        // S = Qs * K^T  (s[i][j]: row 4ty+i, col 4tx+j)
        float s[4][4];
#pragma unroll
        for (int i = 0; i < 4; i++)
#pragma unroll
            for (int j = 0; j < 4; j++) s[i][j] = 0.0f;

#pragma unroll 8
        for (int d = 0; d < 64; d++) {
            float4 rk = *(const float4*)&KPs[d * 64 + (tx << 2)];
            float rq0 = Qs[((ty << 2) + 0) * 64 + d];
            float rq1 = Qs[((ty << 2) + 1) * 64 + d];
            float rq2 = Qs[((ty << 2) + 2) * 64 + d];
            float rq3 = Qs[((ty << 2) + 3) * 64 + d];
            s[0][0] += rq0 * rk.x; s[0][1] += rq0 * rk.y; s[0][2] += rq0 * rk.z; s[0][3] += rq0 * rk.w;
            s[1][0] += rq1 * rk.x; s[1][1] += rq1 * rk.y; s[1][2] += rq1 * rk.z; s[1][3] += rq1 * rk.w;
            s[2][0] += rq2 * rk.x; s[2][1] += rq2 * rk.y; s[2][2] += rq2 * rk.z; s[2][3] += rq2 * rk.w;
            s[3][0] += rq3 * rk.x; s[3][1] += rq3 * rk.y; s[3][2] += rq3 * rk.z; s[3][3] += rq3 * rk.w;
        }

        // Causal mask (only diagonal tile)
        if (j0 == qt) {
#pragma unroll
            for (int i = 0; i < 4; i++) {
                int r = (ty << 2) + i;
#pragma unroll
                for (int j = 0; j < 4; j++) {
                    int c = (tx << 2) + j;
                    if (c > r) s[i][j] = -1e30f;
                }
            }
        }

        // Online softmax; rows span 16 lanes (same ty) -> shfl reduce
#pragma unroll
        for (int i = 0; i < 4; i++) {
            float mx = fmaxf(fmaxf(s[i][0], s[i][1]), fmaxf(s[i][2], s[i][3]));
#pragma unroll
            for (int off = 8; off >= 1; off >>= 1)
                mx = fmaxf(mx, __shfl_xor_sync(0xffffffffu, mx, off));
            float mnew = fmaxf(m_i[i], mx);
            float alpha = __expf(m_i[i] - mnew);
            float rs = 0.0f;
#pragma unroll
            for (int j = 0; j < 4; j++) {
                s[i][j] = __expf(s[i][j] - mnew);
                rs += s[i][j];
            }
#pragma unroll
            for (int off = 8; off >= 1; off >>= 1)
                rs += __shfl_xor_sync(0xffffffffu, rs, off);
            l_i[i] = l_i[i] * alpha + rs;
            m_i[i] = mnew;
#pragma unroll
            for (int j = 0; j < 4; j++) o[i][j] *= alpha;
        }

        __syncthreads();   // everyone done reading KPs as K^T
        // Write P into KPs as [r][c]
#pragma unroll
        for (int i = 0; i < 4; i++)
#pragma unroll
            for (int j = 0; j < 4; j++)
                KPs[((ty << 2) + i) * 64 + (tx << 2) + j] = s[i][j];
        __syncthreads();

        // O += P * V  (o[i][j]: row 4ty+i, dcol 4tx+j)
#pragma unroll 8
        for (int c = 0; c < 64; c++) {
            float4 rv = *(const float4*)&Vs[c * 64 + (tx << 2)];
            float rp0 = KPs[((ty << 2) + 0) * 64 + c];
            float rp1 = KPs[((ty << 2) + 1) * 64 + c];
            float rp2 = KPs[((ty << 2) + 2) * 64 + c];
            float rp3 = KPs[((ty << 2) + 3) * 64 + c];
            o[0][0] += rp0 * rv.x; o[0][1] += rp0 * rv.y; o[0][2] += rp0 * rv.z; o[0][3] += rp0 * rv.w;
            o[1][0] += rp1 * rv.x; o[1][1] += rp1 * rv.y; o[1][2] += rp1 * rv.z; o[1][3] += rp1 * rv.w;
            o[2][0] += rp2 * rv.x; o[2][1] += rp2 * rv.y; o[2][2] += rp2 * rv.z; o[2][3] += rp2 * rv.w;
            o[3][0] += rp3 * rv.x; o[3][1] += rp3 * rv.y; o[3][2] += rp3 * rv.z; o[3][3] += rp3 * rv.w;
        }
    }

    // Epilogue: normalize and write to g_A as [B, T, H*Dk]
    const int b = bh >> 4;
    const int h = bh & 15;
#pragma unroll
    for (int i = 0; i < 4; i++) {
        float inv = 1.0f / l_i[i];
        int t = (qt << 6) + (ty << 2) + i;
        float* arow = g_A + ((size_t)(b * SEQ_T + t) * D_EMB) + (h << 6) + (tx << 2);
#pragma unroll
        for (int j = 0; j < 4; j++) arow[j] = o[i][j] * inv;
    }
}

// ---------------------------------------------------------------------------
extern "C" void kernel_launch(void* const* d_in, const int* in_sizes, int n_in,
                              void* d_out, int out_size) {
    const float* X  = (const float*)d_in[0];
    const float* Wq = (const float*)d_in[1];
    const float* Wk = (const float*)d_in[2];
    const float* Wv = (const float*)d_in[3];
    const float* Wo = (const float*)d_in[4];
    float* out = (float*)d_out;

    float* gA_ptr;
    cudaGetSymbolAddress((void**)&gA_ptr, g_A);

    // 1) QKV projections: X[4096,1024] @ {Wq,Wk,Wv} -> g_Q/g_K/g_V [B,H,T,Dk]
    dim3 gq(D_EMB / 64, M_TOT / 64, 3);
    mha_gemm_kernel<0><<<gq, 256>>>(X, Wq, Wk, Wv, nullptr);

    // 2) Causal flash attention -> g_A [B,T,H*Dk]
    dim3 ga(SEQ_T / 64, BATCH * NHEAD);
    mha_attn_kernel<<<ga, 256>>>();

    // 3) Output projection: g_A @ Wo -> out
    dim3 go(D_EMB / 64, M_TOT / 64);
    mha_gemm_kernel<1><<<go, 256>>>(gA_ptr, Wo, nullptr, nullptr, out);
}

// round 2
// speedup vs baseline: 2.6654x; 2.6654x over previous
#include <cuda_runtime.h>
#include <math.h>

#define D_EMB   1024
#define SEQ_T   2048
#define BATCH   2
#define NHEAD   16
#define DK      64
#define M_TOT   (BATCH * SEQ_T)

// Scratch (device globals: allocation-free rule)
__device__ float g_Q[(size_t)BATCH * NHEAD * SEQ_T * DK];   // [B,H,T,Dk]
__device__ float g_K[(size_t)BATCH * NHEAD * SEQ_T * DK];
__device__ float g_V[(size_t)BATCH * NHEAD * SEQ_T * DK];
__device__ float g_A[(size_t)M_TOT * D_EMB];                // [B,T,H*Dk]

// round-to-nearest fp32 -> tf32 (kept in a float register, bits are tf32)
__device__ __forceinline__ float f2tf(float x) {
    unsigned u;
    asm("cvt.rna.tf32.f32 %0, %1;" : "=r"(u) : "f"(x));
    return __uint_as_float(u);
}

// D += A(16x8) * B(8x8), tf32 inputs as float-bit regs
__device__ __forceinline__ void mma8(float c[4], float a0, float a1, float a2, float a3,
                                     float b0, float b1) {
    unsigned A0 = __float_as_uint(a0), A1 = __float_as_uint(a1);
    unsigned A2 = __float_as_uint(a2), A3 = __float_as_uint(a3);
    unsigned B0 = __float_as_uint(b0), B1 = __float_as_uint(b1);
    asm volatile(
        "mma.sync.aligned.m16n8k8.row.col.f32.tf32.tf32.f32 "
        "{%0,%1,%2,%3},{%4,%5,%6,%7},{%8,%9},{%0,%1,%2,%3};\n"
        : "+f"(c[0]), "+f"(c[1]), "+f"(c[2]), "+f"(c[3])
        : "r"(A0), "r"(A1), "r"(A2), "r"(A3), "r"(B0), "r"(B1));
}

// ---------------------------------------------------------------------------
// Tensor-core GEMM: C[M,1024] = A[M,1024] * W[1024,1024]
// 128x128 block tile, BK=16, 256 thr (8 warps, 2x4), warp tile 64x32,
// double-buffered smem, k-major layouts stride 136 (conflict-free frags).
// MODE 0: QKV projection (blockIdx.z picks W, epilogue remaps to [B,H,T,Dk])
// MODE 1: plain row-major store
// ---------------------------------------------------------------------------
template <int MODE>
__global__ __launch_bounds__(256) void gemm_tc(const float* __restrict__ A,
                                               const float* __restrict__ W0,
                                               const float* __restrict__ W1,
                                               const float* __restrict__ W2,
                                               float* __restrict__ Cout) {
    const float* W;
    float* dst;
    if (MODE == 0) {
        if (blockIdx.z == 0)      { W = W0; dst = g_Q; }
        else if (blockIdx.z == 1) { W = W1; dst = g_K; }
        else                      { W = W2; dst = g_V; }
    } else {
        W = W0; dst = Cout;
    }

    __shared__ float As[2][16][136];   // [k][m]
    __shared__ float Bs[2][16][136];   // [k][n]

    const int tid  = threadIdx.x;
    const int lane = tid & 31;
    const int wrp  = tid >> 5;
    const int wr   = wrp >> 2;        // 0..1 (64 rows)
    const int wc   = wrp & 3;         // 0..3 (32 cols)
    const int m0   = blockIdx.y << 7;
    const int n0   = blockIdx.x << 7;

    // global load mapping
    const int am = tid >> 1;              // 0..127
    const int ak = (tid & 1) << 3;        // 0 or 8
    const int bk = tid >> 4;              // 0..15
    const int bn = (tid & 15) << 2;       // 0..60

    const float* Ag = A + (size_t)(m0 + am) * D_EMB + ak;
    const float* Bg = W + (size_t)bk * D_EMB + n0 + bn;

    float acc[4][4][4];
#pragma unroll
    for (int mi = 0; mi < 4; mi++)
#pragma unroll
        for (int ni = 0; ni < 4; ni++)
#pragma unroll
            for (int c = 0; c < 4; c++) acc[mi][ni][c] = 0.0f;

    // prologue: tile 0 -> smem[0]
    {
        float4 av0 = *(const float4*)(Ag);
        float4 av1 = *(const float4*)(Ag + 4);
        float4 bv0 = *(const float4*)(Bg);
        float4 bv1 = *(const float4*)(Bg + 64);
        As[0][ak + 0][am] = f2tf(av0.x); As[0][ak + 1][am] = f2tf(av0.y);
        As[0][ak + 2][am] = f2tf(av0.z); As[0][ak + 3][am] = f2tf(av0.w);
        As[0][ak + 4][am] = f2tf(av1.x); As[0][ak + 5][am] = f2tf(av1.y);
        As[0][ak + 6][am] = f2tf(av1.z); As[0][ak + 7][am] = f2tf(av1.w);
        Bs[0][bk][bn + 0]  = f2tf(bv0.x); Bs[0][bk][bn + 1]  = f2tf(bv0.y);
        Bs[0][bk][bn + 2]  = f2tf(bv0.z); Bs[0][bk][bn + 3]  = f2tf(bv0.w);
        Bs[0][bk][bn + 64] = f2tf(bv1.x); Bs[0][bk][bn + 65] = f2tf(bv1.y);
        Bs[0][bk][bn + 66] = f2tf(bv1.z); Bs[0][bk][bn + 67] = f2tf(bv1.w);
    }
    __syncthreads();

    const int NK = D_EMB / 16;   // 64
    for (int kt = 0; kt < NK; kt++) {
        const int cur = kt & 1;
        float4 av0, av1, bv0, bv1;
        if (kt + 1 < NK) {
            av0 = *(const float4*)(Ag + (kt + 1) * 16);
            av1 = *(const float4*)(Ag + (kt + 1) * 16 + 4);
            bv0 = *(const float4*)(Bg + (size_t)(kt + 1) * 16 * D_EMB);
            bv1 = *(const float4*)(Bg + (size_t)(kt + 1) * 16 * D_EMB + 64);
        }

        // compute on smem[cur]
#pragma unroll
        for (int ks = 0; ks < 2; ks++) {
            const int kb = ks * 8 + (lane & 3);
            float a[4][4];
#pragma unroll
            for (int mi = 0; mi < 4; mi++) {
                const int row = wr * 64 + mi * 16 + (lane >> 2);
                a[mi][0] = As[cur][kb][row];
                a[mi][1] = As[cur][kb][row + 8];
                a[mi][2] = As[cur][kb + 4][row];
                a[mi][3] = As[cur][kb + 4][row + 8];
            }
            float b[4][2];
#pragma unroll
            for (int ni = 0; ni < 4; ni++) {
                const int col = wc * 32 + ni * 8 + (lane >> 2);
                b[ni][0] = Bs[cur][kb][col];
                b[ni][1] = Bs[cur][kb + 4][col];
            }
#pragma unroll
            for (int mi = 0; mi < 4; mi++)
#pragma unroll
                for (int ni = 0; ni < 4; ni++)
                    mma8(acc[mi][ni], a[mi][0], a[mi][1], a[mi][2], a[mi][3],
                         b[ni][0], b[ni][1]);
        }

        if (kt + 1 < NK) {
            const int nxt = cur ^ 1;
            As[nxt][ak + 0][am] = f2tf(av0.x); As[nxt][ak + 1][am] = f2tf(av0.y);
            As[nxt][ak + 2][am] = f2tf(av0.z); As[nxt][ak + 3][am] = f2tf(av0.w);
            As[nxt][ak + 4][am] = f2tf(av1.x); As[nxt][ak + 5][am] = f2tf(av1.y);
            As[nxt][ak + 6][am] = f2tf(av1.z); As[nxt][ak + 7][am] = f2tf(av1.w);
            Bs[nxt][bk][bn + 0]  = f2tf(bv0.x); Bs[nxt][bk][bn + 1]  = f2tf(bv0.y);
            Bs[nxt][bk][bn + 2]  = f2tf(bv0.z); Bs[nxt][bk][bn + 3]  = f2tf(bv0.w);
            Bs[nxt][bk][bn + 64] = f2tf(bv1.x); Bs[nxt][bk][bn + 65] = f2tf(bv1.y);
            Bs[nxt][bk][bn + 66] = f2tf(bv1.z); Bs[nxt][bk][bn + 67] = f2tf(bv1.w);
        }
        __syncthreads();
    }

    // epilogue
#pragma unroll
    for (int mi = 0; mi < 4; mi++) {
        const int row0 = m0 + wr * 64 + mi * 16 + (lane >> 2);
#pragma unroll
        for (int ni = 0; ni < 4; ni++) {
            const int col = n0 + wc * 32 + ni * 8 + ((lane & 3) << 1);
            if (MODE == 0) {
                const int h = col >> 6, d = col & 63;
                {
                    const int b = row0 >> 11, t = row0 & 2047;
                    float2 v = make_float2(acc[mi][ni][0], acc[mi][ni][1]);
                    *(float2*)&dst[((size_t)((b << 4) + h) * SEQ_T + t) * DK + d] = v;
                }
                {
                    const int r1 = row0 + 8;
                    const int b = r1 >> 11, t = r1 & 2047;
                    float2 v = make_float2(acc[mi][ni][2], acc[mi][ni][3]);
                    *(float2*)&dst[((size_t)((b << 4) + h) * SEQ_T + t) * DK + d] = v;
                }
            } else {
                *(float2*)&dst[(size_t)row0 * D_EMB + col] =
                    make_float2(acc[mi][ni][0], acc[mi][ni][1]);
                *(float2*)&dst[(size_t)(row0 + 8) * D_EMB + col] =
                    make_float2(acc[mi][ni][2], acc[mi][ni][3]);
            }
        }
    }
}

// ---------------------------------------------------------------------------
// Tensor-core causal flash attention.
// Block: 256 thr (8 warps), q-tile 128 (16 rows/warp), kv-tile 64, Dk=64.
// Dynamic smem: Qs[d64][q136] + Ks[d64][kv72] + Vs[kv64][d72] + Ps[kv64][q136]
// ---------------------------------------------------------------------------
#define QS_OFF 0
#define KS_OFF (64 * 136)
#define VS_OFF (KS_OFF + 64 * 72)
#define PS_OFF (VS_OFF + 64 * 72)
#define ATTN_SMEM_FLOATS (PS_OFF + 64 * 136)

__global__ __launch_bounds__(256) void mha_attn_tc() {
    extern __shared__ float sm[];
    float* Qs = sm + QS_OFF;   // [d][q]
    float* Ks = sm + KS_OFF;   // [d][kv]
    float* Vs = sm + VS_OFF;   // [kv][d]
    float* Ps = sm + PS_OFF;   // [kv][q]

    const int tid  = threadIdx.x;
    const int lane = tid & 31;
    const int w    = tid >> 5;        // 0..7 -> q rows [16w,16w+16)
    const int qt   = blockIdx.x;      // q tile of 128
    const int bh   = blockIdx.y;
    const int qbase = qt << 7;

    const float* Qg = g_Q + (size_t)bh * (SEQ_T * DK) + (size_t)qbase * DK;
    const float* Kg = g_K + (size_t)bh * (SEQ_T * DK);
    const float* Vg = g_V + (size_t)bh * (SEQ_T * DK);

    // load Q tile once (scaled by 1/sqrt(64)=0.125), transposed to [d][q]
    for (int e = tid; e < 2048; e += 256) {
        const int r = e >> 4;
        const int d4 = (e & 15) << 2;
        float4 v = *(const float4*)(Qg + r * DK + d4);
        Qs[(d4 + 0) * 136 + r] = f2tf(0.125f * v.x);
        Qs[(d4 + 1) * 136 + r] = f2tf(0.125f * v.y);
        Qs[(d4 + 2) * 136 + r] = f2tf(0.125f * v.z);
        Qs[(d4 + 3) * 136 + r] = f2tf(0.125f * v.w);
    }

    float o[8][4];
#pragma unroll
    for (int di = 0; di < 8; di++)
#pragma unroll
        for (int c = 0; c < 4; c++) o[di][c] = 0.0f;
    float m0 = -1e30f, m1 = -1e30f, l0 = 0.0f, l1 = 0.0f;

    const int jmax = 2 * qt + 1;
    for (int j0 = 0; j0 <= jmax; j0++) {
        __syncthreads();   // prev-iter reads of Ks/Vs done; Q ready (first iter via 2nd sync)

        // load K tile transposed -> Ks[d][kv], V straight -> Vs[kv][d]
        for (int e = tid; e < 1024; e += 256) {
            const int r = e >> 4;              // kv row 0..63
            const int d4 = (e & 15) << 2;
            float4 kv = *(const float4*)(Kg + (size_t)(j0 * 64 + r) * DK + d4);
            Ks[(d4 + 0) * 72 + r] = f2tf(kv.x);
            Ks[(d4 + 1) * 72 + r] = f2tf(kv.y);
            Ks[(d4 + 2) * 72 + r] = f2tf(kv.z);
            Ks[(d4 + 3) * 72 + r] = f2tf(kv.w);
            float4 vv = *(const float4*)(Vg + (size_t)(j0 * 64 + r) * DK + d4);
            vv.x = f2tf(vv.x); vv.y = f2tf(vv.y); vv.z = f2tf(vv.z); vv.w = f2tf(vv.w);
            *(float4*)&Vs[r * 72 + d4] = vv;
        }
        __syncthreads();

        // S = Q * K^T   (warp: 16 q rows x 64 kv cols)
        float s[8][4];
#pragma unroll
        for (int ni = 0; ni < 8; ni++)
#pragma unroll
            for (int c = 0; c < 4; c++) s[ni][c] = 0.0f;

#pragma unroll
        for (int kk = 0; kk < 8; kk++) {
            const int kb = kk * 8 + (lane & 3);
            const int qc = w * 16 + (lane >> 2);
            const float a0 = Qs[kb * 136 + qc];
            const float a1 = Qs[kb * 136 + qc + 8];
            const float a2 = Qs[(kb + 4) * 136 + qc];
            const float a3 = Qs[(kb + 4) * 136 + qc + 8];
#pragma unroll
            for (int ni = 0; ni < 8; ni++) {
                const float b0 = Ks[kb * 72 + ni * 8 + (lane >> 2)];
                const float b1 = Ks[(kb + 4) * 72 + ni * 8 + (lane >> 2)];
                mma8(s[ni], a0, a1, a2, a3, b0, b1);
            }
        }

        // causal mask (only possible on the top two tiles)
        if (j0 >= 2 * qt) {
            const int r0g = qbase + w * 16 + (lane >> 2);
            const int r1g = r0g + 8;
            const int cb = j0 * 64 + ((lane & 3) << 1);
#pragma unroll
            for (int ni = 0; ni < 8; ni++) {
                const int c0 = cb + ni * 8;
                if (c0 > r0g)     s[ni][0] = -1e30f;
                if (c0 + 1 > r0g) s[ni][1] = -1e30f;
                if (c0 > r1g)     s[ni][2] = -1e30f;
                if (c0 + 1 > r1g) s[ni][3] = -1e30f;
            }
        }

        // online softmax (rows split: regs {0,1}=row0, {2,3}=row1; quad shfl)
        float mx0 = -1e30f, mx1 = -1e30f;
#pragma unroll
        for (int ni = 0; ni < 8; ni++) {
            mx0 = fmaxf(mx0, fmaxf(s[ni][0], s[ni][1]));
            mx1 = fmaxf(mx1, fmaxf(s[ni][2], s[ni][3]));
        }
        mx0 = fmaxf(mx0, __shfl_xor_sync(0xffffffffu, mx0, 1));
        mx0 = fmaxf(mx0, __shfl_xor_sync(0xffffffffu, mx0, 2));
        mx1 = fmaxf(mx1, __shfl_xor_sync(0xffffffffu, mx1, 1));
        mx1 = fmaxf(mx1, __shfl_xor_sync(0xffffffffu, mx1, 2));

        const float mn0 = fmaxf(m0, mx0);
        const float mn1 = fmaxf(m1, mx1);
        const float al0 = __expf(m0 - mn0);
        const float al1 = __expf(m1 - mn1);
        float rs0 = 0.0f, rs1 = 0.0f;
#pragma unroll
        for (int ni = 0; ni < 8; ni++) {
            s[ni][0] = __expf(s[ni][0] - mn0); rs0 += s[ni][0];
            s[ni][1] = __expf(s[ni][1] - mn0); rs0 += s[ni][1];
            s[ni][2] = __expf(s[ni][2] - mn1); rs1 += s[ni][2];
            s[ni][3] = __expf(s[ni][3] - mn1); rs1 += s[ni][3];
        }
        rs0 += __shfl_xor_sync(0xffffffffu, rs0, 1);
        rs0 += __shfl_xor_sync(0xffffffffu, rs0, 2);
        rs1 += __shfl_xor_sync(0xffffffffu, rs1, 1);
        rs1 += __shfl_xor_sync(0xffffffffu, rs1, 2);
        l0 = l0 * al0 + rs0; m0 = mn0;
        l1 = l1 * al1 + rs1; m1 = mn1;
#pragma unroll
        for (int di = 0; di < 8; di++) {
            o[di][0] *= al0; o[di][1] *= al0;
            o[di][2] *= al1; o[di][3] *= al1;
        }

        // P -> smem (warp-private q rows, so only __syncwarp needed)
        {
            const int q0 = w * 16 + (lane >> 2);
            const int cb = (lane & 3) << 1;
#pragma unroll
            for (int ni = 0; ni < 8; ni++) {
                const int c = ni * 8 + cb;
                Ps[c * 136 + q0]           = f2tf(s[ni][0]);
                Ps[(c + 1) * 136 + q0]     = f2tf(s[ni][1]);
                Ps[c * 136 + q0 + 8]       = f2tf(s[ni][2]);
                Ps[(c + 1) * 136 + q0 + 8] = f2tf(s[ni][3]);
            }
        }
        __syncwarp();

        // O += P * V
#pragma unroll
        for (int kk = 0; kk < 8; kk++) {
            const int kb = kk * 8 + (lane & 3);
            const int qc = w * 16 + (lane >> 2);
            const float a0 = Ps[kb * 136 + qc];
            const float a1 = Ps[kb * 136 + qc + 8];
            const float a2 = Ps[(kb + 4) * 136 + qc];
            const float a3 = Ps[(kb + 4) * 136 + qc + 8];
#pragma unroll
            for (int di = 0; di < 8; di++) {
                const float b0 = Vs[kb * 72 + di * 8 + (lane >> 2)];
                const float b1 = Vs[(kb + 4) * 72 + di * 8 + (lane >> 2)];
                mma8(o[di], a0, a1, a2, a3, b0, b1);
            }
        }
    }

    // epilogue -> g_A [B, T, H*Dk]
    const int b = bh >> 4;
    const int h = bh & 15;
    const float inv0 = 1.0f / l0;
    const float inv1 = 1.0f / l1;
    const int t0 = qbase + w * 16 + (lane >> 2);
    const int t1 = t0 + 8;
#pragma unroll
    for (int di = 0; di < 8; di++) {
        const int d = di * 8 + ((lane & 3) << 1);
        *(float2*)&g_A[(size_t)(b * SEQ_T + t0) * D_EMB + (h << 6) + d] =
            make_float2(o[di][0] * inv0, o[di][1] * inv0);
        *(float2*)&g_A[(size_t)(b * SEQ_T + t1) * D_EMB + (h << 6) + d] =
            make_float2(o[di][2] * inv1, o[di][3] * inv1);
    }
}

// ---------------------------------------------------------------------------
extern "C" void kernel_launch(void* const* d_in, const int* in_sizes, int n_in,
                              void* d_out, int out_size) {
    const float* X  = (const float*)d_in[0];
    const float* Wq = (const float*)d_in[1];
    const float* Wk = (const float*)d_in[2];
    const float* Wv = (const float*)d_in[3];
    const float* Wo = (const float*)d_in[4];
    float* out = (float*)d_out;

    float* gA_ptr;
    cudaGetSymbolAddress((void**)&gA_ptr, g_A);

    static bool attr_set = false;
    if (!attr_set) {
        cudaFuncSetAttribute(mha_attn_tc, cudaFuncAttributeMaxDynamicSharedMemorySize,
                             ATTN_SMEM_FLOATS * sizeof(float));
        attr_set = true;
    }

    // 1) QKV projections
    dim3 gq(D_EMB / 128, M_TOT / 128, 3);
    gemm_tc<0><<<gq, 256>>>(X, Wq, Wk, Wv, nullptr);

    // 2) causal flash attention
    dim3 ga(SEQ_T / 128, BATCH * NHEAD);
    mha_attn_tc<<<ga, 256, ATTN_SMEM_FLOATS * sizeof(float)>>>();

    // 3) output projection
    dim3 go(D_EMB / 128, M_TOT / 128);
    gemm_tc<1><<<go, 256>>>(gA_ptr, Wo, nullptr, nullptr, out);
}

// round 3
// speedup vs baseline: 6.2087x; 2.3294x over previous
#include <cuda_runtime.h>
#include <cuda_fp16.h>
#include <math.h>

#define D_EMB   1024
#define SEQ_T   2048
#define BATCH   2
#define NHEAD   16
#define DK      64
#define M_TOT   (BATCH * SEQ_T)

// ---------------- device scratch (allocation-free rule) ----------------
__device__ __half g_Xh[(size_t)M_TOT * D_EMB];              // X in half
__device__ __half g_Wt[4ULL * D_EMB * D_EMB];               // W^T half: [z][n][k]
__device__ __half g_Q[(size_t)BATCH * NHEAD * SEQ_T * DK];  // [B,H,T,Dk], pre-scaled
__device__ __half g_K[(size_t)BATCH * NHEAD * SEQ_T * DK];  // [B,H,T,Dk]
__device__ __half g_V[(size_t)BATCH * NHEAD * DK * SEQ_T];  // [B,H,Dk,T] (transposed)
__device__ __half g_A[(size_t)M_TOT * D_EMB];               // [B,T,H*Dk]

// ---------------- small helpers ----------------
__device__ __forceinline__ void cp16(void* dst, const void* src) {
    unsigned s = (unsigned)__cvta_generic_to_shared(dst);
    asm volatile("cp.async.cg.shared.global [%0], [%1], 16;" :: "r"(s), "l"(src));
}
__device__ __forceinline__ void cp_commit() { asm volatile("cp.async.commit_group;"); }
template <int N>
__device__ __forceinline__ void cp_wait() { asm volatile("cp.async.wait_group %0;" :: "n"(N)); }

// D += A(16x16) * B(16x8), fp16 in, fp32 accum
__device__ __forceinline__ void mma16(float* c, unsigned a0, unsigned a1, unsigned a2,
                                      unsigned a3, unsigned b0, unsigned b1) {
    asm volatile(
        "mma.sync.aligned.m16n8k16.row.col.f32.f16.f16.f32 "
        "{%0,%1,%2,%3},{%4,%5,%6,%7},{%8,%9},{%0,%1,%2,%3};\n"
        : "+f"(c[0]), "+f"(c[1]), "+f"(c[2]), "+f"(c[3])
        : "r"(a0), "r"(a1), "r"(a2), "r"(a3), "r"(b0), "r"(b1));
}
__device__ __forceinline__ unsigned h2u(float x, float y) {
    __half2 h = __floats2half2_rn(x, y);
    return *(unsigned*)&h;
}

// ---------------- converters ----------------
__global__ void cvt_x_kernel(const float* __restrict__ X) {
    const int i = blockIdx.x * 256 + threadIdx.x;   // float4 index
    float4 v = ((const float4*)X)[i];
    __half2* d = (__half2*)g_Xh + (size_t)i * 2;
    d[0] = __floats2half2_rn(v.x, v.y);
    d[1] = __floats2half2_rn(v.z, v.w);
}

// W [k][n] fp32 -> g_Wt[z] [n][k] half, 32x32 tiles
__global__ void cvt_w_kernel(const float* __restrict__ W0, const float* __restrict__ W1,
                             const float* __restrict__ W2, const float* __restrict__ W3) {
    __shared__ float Ws[32][33];
    const int z = blockIdx.z;
    const float* W = (z == 0) ? W0 : (z == 1) ? W1 : (z == 2) ? W2 : W3;
    __half* dst = g_Wt + (size_t)z * D_EMB * D_EMB;
    const int kb = blockIdx.y << 5;
    const int nb = blockIdx.x << 5;
    const int tid = threadIdx.x;

    {   // load 32x32 fp32 tile
        const int r = tid >> 3;
        const int c4 = (tid & 7) << 2;
        float4 v = *(const float4*)&W[(size_t)(kb + r) * D_EMB + nb + c4];
        Ws[r][c4 + 0] = v.x; Ws[r][c4 + 1] = v.y; Ws[r][c4 + 2] = v.z; Ws[r][c4 + 3] = v.w;
    }
    __syncthreads();
#pragma unroll
    for (int it = 0; it < 2; it++) {   // write transposed as half2
        const int e = tid + it * 256;
        const int n = e >> 4;
        const int k2 = (e & 15) << 1;
        __half2 h = __floats2half2_rn(Ws[k2][n], Ws[k2 + 1][n]);
        *(__half2*)&dst[(size_t)(nb + n) * D_EMB + kb + k2] = h;
    }
}

// ---------------- fp16 tensor-core GEMM ----------------
// C[M,1024] = A[M,1024] * W[1024,1024]; 128x128 tile, BK=32, 8 warps (2x4),
// warp tile 64x32. Swizzled smem (16B chunks XOR (row>>1)&3), cp.async 2-stage.
// MODE 0: A=g_Xh, B=g_Wt[z]; epilogue -> g_Q (x0.125)/g_K/[g_V transposed]
// MODE 1: A=g_A,  B=g_Wt[3]; epilogue -> fp32 out
#define GSWZ(r, c) (((r) << 5) + ((((c) ^ (((r) >> 1) & 3))) << 3))

template <int MODE>
__global__ __launch_bounds__(256, 2) void gemm_h(float* __restrict__ out) {
    __shared__ __align__(16) __half As[2][128 * 32];
    __shared__ __align__(16) __half Bs[2][128 * 32];

    const int tid  = threadIdx.x;
    const int lane = tid & 31;
    const int g    = lane >> 2;
    const int t    = lane & 3;
    const int wrp  = tid >> 5;
    const int wr   = wrp >> 2;
    const int wc   = wrp & 3;
    const int m0   = blockIdx.y << 7;
    const int n0   = blockIdx.x << 7;

    const __half* A  = (MODE == 0) ? g_Xh : g_A;
    const __half* Bw = g_Wt + (size_t)((MODE == 0) ? blockIdx.z : 3) * (D_EMB * D_EMB);

    const int lr = tid >> 1;           // 0..127
    const int lc = (tid & 1) << 1;     // chunk base 0 or 2
    const __half* Asrc = A + (size_t)(m0 + lr) * D_EMB;
    const __half* Bsrc = Bw + (size_t)(n0 + lr) * D_EMB;

    float acc[4][4][4];
#pragma unroll
    for (int mi = 0; mi < 4; mi++)
#pragma unroll
        for (int ni = 0; ni < 4; ni++)
#pragma unroll
            for (int c = 0; c < 4; c++) acc[mi][ni][c] = 0.0f;

#pragma unroll
    for (int i = 0; i < 2; i++) {   // prologue: tile 0
        const int c = lc + i;
        cp16(&As[0][GSWZ(lr, c)], Asrc + c * 8);
        cp16(&Bs[0][GSWZ(lr, c)], Bsrc + c * 8);
    }
    cp_commit();

    const int NK = D_EMB / 32;
    for (int kt = 0; kt < NK; kt++) {
        const int cur = kt & 1;
        if (kt + 1 < NK) {
            const int nxt = cur ^ 1;
            const size_t ko = (size_t)(kt + 1) * 32;
#pragma unroll
            for (int i = 0; i < 2; i++) {
                const int c = lc + i;
                cp16(&As[nxt][GSWZ(lr, c)], Asrc + ko + c * 8);
                cp16(&Bs[nxt][GSWZ(lr, c)], Bsrc + ko + c * 8);
            }
            cp_commit();
            cp_wait<1>();
        } else {
            cp_wait<0>();
        }
        __syncthreads();

#pragma unroll
        for (int kk = 0; kk < 2; kk++) {
            unsigned a[4][4];
#pragma unroll
            for (int mi = 0; mi < 4; mi++) {
                const int r0 = wr * 64 + mi * 16 + g;
                a[mi][0] = *(const unsigned*)&As[cur][GSWZ(r0,     2 * kk)     + 2 * t];
                a[mi][1] = *(const unsigned*)&As[cur][GSWZ(r0 + 8, 2 * kk)     + 2 * t];
                a[mi][2] = *(const unsigned*)&As[cur][GSWZ(r0,     2 * kk + 1) + 2 * t];
                a[mi][3] = *(const unsigned*)&As[cur][GSWZ(r0 + 8, 2 * kk + 1) + 2 * t];
            }
            unsigned b[4][2];
#pragma unroll
            for (int ni = 0; ni < 4; ni++) {
                const int nr = wc * 32 + ni * 8 + g;
                b[ni][0] = *(const unsigned*)&Bs[cur][GSWZ(nr, 2 * kk)     + 2 * t];
                b[ni][1] = *(const unsigned*)&Bs[cur][GSWZ(nr, 2 * kk + 1) + 2 * t];
            }
#pragma unroll
            for (int mi = 0; mi < 4; mi++)
#pragma unroll
                for (int ni = 0; ni < 4; ni++)
                    mma16(acc[mi][ni], a[mi][0], a[mi][1], a[mi][2], a[mi][3],
                          b[ni][0], b[ni][1]);
        }
        __syncthreads();
    }

    // epilogue
#pragma unroll
    for (int mi = 0; mi < 4; mi++) {
        const int row0 = m0 + wr * 64 + mi * 16 + g;
#pragma unroll
        for (int ni = 0; ni < 4; ni++) {
            const int col = n0 + wc * 32 + ni * 8 + 2 * t;
            float c0 = acc[mi][ni][0], c1 = acc[mi][ni][1];
            float c2 = acc[mi][ni][2], c3 = acc[mi][ni][3];
            if (MODE == 0) {
                const int z = blockIdx.z;
                if (z == 0) { c0 *= 0.125f; c1 *= 0.125f; c2 *= 0.125f; c3 *= 0.125f; }
                const int h = col >> 6, d = col & 63;
                const int b0i = row0 >> 11, t0 = row0 & 2047;
                const int r1 = row0 + 8;
                const int b1i = r1 >> 11, t1 = r1 & 2047;
                const int bh0 = (b0i << 4) + h;
                const int bh1 = (b1i << 4) + h;
                if (z == 2) {   // V transposed: [B,H,Dk,T]
                    g_V[((size_t)bh0 * DK + d)     * SEQ_T + t0] = __float2half_rn(c0);
                    g_V[((size_t)bh0 * DK + d + 1) * SEQ_T + t0] = __float2half_rn(c1);
                    g_V[((size_t)bh1 * DK + d)     * SEQ_T + t1] = __float2half_rn(c2);
                    g_V[((size_t)bh1 * DK + d + 1) * SEQ_T + t1] = __float2half_rn(c3);
                } else {
                    __half* dst = (z == 0) ? g_Q : g_K;
                    *(__half2*)&dst[((size_t)bh0 * SEQ_T + t0) * DK + d] = __floats2half2_rn(c0, c1);
                    *(__half2*)&dst[((size_t)bh1 * SEQ_T + t1) * DK + d] = __floats2half2_rn(c2, c3);
                }
            } else {
                *(float2*)&out[(size_t)row0 * D_EMB + col]       = make_float2(c0, c1);
                *(float2*)&out[(size_t)(row0 + 8) * D_EMB + col] = make_float2(c2, c3);
            }
        }
    }
}

// ---------------- fp16 causal flash attention ----------------
// Block 256 thr (8 warps), q-tile 128 (16 rows/warp), kv-tile 64, Dk=64.
// P kept in registers (S-frag -> A-frag repack). K/V double-buffered cp.async.
#define ASWZ(r, c) (((r) << 6) + ((((c) ^ ((r) & 7))) << 3))

__global__ __launch_bounds__(256, 2) void attn_h() {
    __shared__ __align__(16) __half Qs[128 * 64];
    __shared__ __align__(16) __half Ks[2][64 * 64];
    __shared__ __align__(16) __half Vs[2][64 * 64];

    const int tid  = threadIdx.x;
    const int lane = tid & 31;
    const int g    = lane >> 2;
    const int t    = lane & 3;
    const int w    = tid >> 5;
    const int qt   = gridDim.x - 1 - blockIdx.x;   // heavy tiles first
    const int bh   = blockIdx.y;
    const int qbase = qt << 7;

    const __half* qg = g_Q + ((size_t)bh * SEQ_T + qbase) * DK;
    const __half* kg = g_K + (size_t)bh * SEQ_T * DK;
    const __half* vg = g_V + (size_t)bh * DK * SEQ_T;

    // prologue: Q tile + KV tile 0
    {
        const int r = tid >> 1;
        const int cb = (tid & 1) << 2;
#pragma unroll
        for (int i = 0; i < 4; i++) {
            const int c = cb + i;
            cp16(&Qs[ASWZ(r, c)], qg + (size_t)r * DK + c * 8);
        }
    }
    {
        const int r = tid >> 2;
        const int cb = (tid & 3) << 1;
#pragma unroll
        for (int i = 0; i < 2; i++) {
            const int c = cb + i;
            cp16(&Ks[0][ASWZ(r, c)], kg + (size_t)r * DK + c * 8);
            cp16(&Vs[0][ASWZ(r, c)], vg + (size_t)r * SEQ_T + c * 8);
        }
    }
    cp_commit();

    float o[8][4];
#pragma unroll
    for (int di = 0; di < 8; di++)
#pragma unroll
        for (int c = 0; c < 4; c++) o[di][c] = 0.0f;
    float m0 = -1e30f, m1 = -1e30f, l0 = 0.0f, l1 = 0.0f;

    const int jmax = 2 * qt + 1;
    for (int j0 = 0; j0 <= jmax; j0++) {
        const int cur = j0 & 1;
        if (j0 + 1 <= jmax) {
            const int nxt = cur ^ 1;
            const int r = tid >> 2;
            const int cb = (tid & 3) << 1;
#pragma unroll
            for (int i = 0; i < 2; i++) {
                const int c = cb + i;
                cp16(&Ks[nxt][ASWZ(r, c)], kg + (size_t)((j0 + 1) * 64 + r) * DK + c * 8);
                cp16(&Vs[nxt][ASWZ(r, c)], vg + (size_t)r * SEQ_T + (j0 + 1) * 64 + c * 8);
            }
            cp_commit();
            cp_wait<1>();
        } else {
            cp_wait<0>();
        }
        __syncthreads();

        // S = Q * K^T  (warp: 16 q rows x 64 kv)
        float s[8][4];
#pragma unroll
        for (int ni = 0; ni < 8; ni++)
#pragma unroll
            for (int c = 0; c < 4; c++) s[ni][c] = 0.0f;

#pragma unroll
        for (int kk = 0; kk < 4; kk++) {
            const int qr = w * 16 + g;
            const unsigned a0 = *(const unsigned*)&Qs[ASWZ(qr,     2 * kk)     + 2 * t];
            const unsigned a1 = *(const unsigned*)&Qs[ASWZ(qr + 8, 2 * kk)     + 2 * t];
            const unsigned a2 = *(const unsigned*)&Qs[ASWZ(qr,     2 * kk + 1) + 2 * t];
            const unsigned a3 = *(const unsigned*)&Qs[ASWZ(qr + 8, 2 * kk + 1) + 2 * t];
#pragma unroll
            for (int ni = 0; ni < 8; ni++) {
                const int kr = ni * 8 + g;
                const unsigned b0 = *(const unsigned*)&Ks[cur][ASWZ(kr, 2 * kk)     + 2 * t];
                const unsigned b1 = *(const unsigned*)&Ks[cur][ASWZ(kr, 2 * kk + 1) + 2 * t];
                mma16(s[ni], a0, a1, a2, a3, b0, b1);
            }
        }

        // causal mask (only top two kv tiles can cross the diagonal)
        if (j0 >= 2 * qt) {
            const int r0g = qbase + w * 16 + g;
            const int r1g = r0g + 8;
            const int cb = j0 * 64 + 2 * t;
#pragma unroll
            for (int ni = 0; ni < 8; ni++) {
                const int c0 = cb + ni * 8;
                if (c0 > r0g)     s[ni][0] = -1e30f;
                if (c0 + 1 > r0g) s[ni][1] = -1e30f;
                if (c0 > r1g)     s[ni][2] = -1e30f;
                if (c0 + 1 > r1g) s[ni][3] = -1e30f;
            }
        }

        // online softmax (regs {0,1}=row g, {2,3}=row g+8; quad shfl)
        float mx0 = -1e30f, mx1 = -1e30f;
#pragma unroll
        for (int ni = 0; ni < 8; ni++) {
            mx0 = fmaxf(mx0, fmaxf(s[ni][0], s[ni][1]));
            mx1 = fmaxf(mx1, fmaxf(s[ni][2], s[ni][3]));
        }
        mx0 = fmaxf(mx0, __shfl_xor_sync(0xffffffffu, mx0, 1));
        mx0 = fmaxf(mx0, __shfl_xor_sync(0xffffffffu, mx0, 2));
        mx1 = fmaxf(mx1, __shfl_xor_sync(0xffffffffu, mx1, 1));
        mx1 = fmaxf(mx1, __shfl_xor_sync(0xffffffffu, mx1, 2));

        const float mn0 = fmaxf(m0, mx0);
        const float mn1 = fmaxf(m1, mx1);
        const float al0 = __expf(m0 - mn0);
        const float al1 = __expf(m1 - mn1);
        float rs0 = 0.0f, rs1 = 0.0f;
#pragma unroll
        for (int ni = 0; ni < 8; ni++) {
            s[ni][0] = __expf(s[ni][0] - mn0); rs0 += s[ni][0];
            s[ni][1] = __expf(s[ni][1] - mn0); rs0 += s[ni][1];
            s[ni][2] = __expf(s[ni][2] - mn1); rs1 += s[ni][2];
            s[ni][3] = __expf(s[ni][3] - mn1); rs1 += s[ni][3];
        }
        rs0 += __shfl_xor_sync(0xffffffffu, rs0, 1);
        rs0 += __shfl_xor_sync(0xffffffffu, rs0, 2);
        rs1 += __shfl_xor_sync(0xffffffffu, rs1, 1);
        rs1 += __shfl_xor_sync(0xffffffffu, rs1, 2);
        l0 = l0 * al0 + rs0; m0 = mn0;
        l1 = l1 * al1 + rs1; m1 = mn1;
#pragma unroll
        for (int di = 0; di < 8; di++) {
            o[di][0] *= al0; o[di][1] *= al0;
            o[di][2] *= al1; o[di][3] *= al1;
        }

        // O += P * V, P repacked from S accumulators (registers only)
#pragma unroll
        for (int kk = 0; kk < 4; kk++) {
            const unsigned a0 = h2u(s[2 * kk][0],     s[2 * kk][1]);
            const unsigned a1 = h2u(s[2 * kk][2],     s[2 * kk][3]);
            const unsigned a2 = h2u(s[2 * kk + 1][0], s[2 * kk + 1][1]);
            const unsigned a3 = h2u(s[2 * kk + 1][2], s[2 * kk + 1][3]);
#pragma unroll
            for (int di = 0; di < 8; di++) {
                const int vr = di * 8 + g;
                const unsigned b0 = *(const unsigned*)&Vs[cur][ASWZ(vr, 2 * kk)     + 2 * t];
                const unsigned b1 = *(const unsigned*)&Vs[cur][ASWZ(vr, 2 * kk + 1) + 2 * t];
                mma16(o[di], a0, a1, a2, a3, b0, b1);
            }
        }
        __syncthreads();
    }

    // epilogue -> g_A [B,T,H*Dk] half
    const int b = bh >> 4;
    const int h = bh & 15;
    const float inv0 = 1.0f / l0;
    const float inv1 = 1.0f / l1;
    const int t0 = qbase + w * 16 + g;
    const int t1 = t0 + 8;
#pragma unroll
    for (int di = 0; di < 8; di++) {
        const int d = di * 8 + 2 * t;
        *(__half2*)&g_A[((size_t)(b * SEQ_T + t0)) * D_EMB + (h << 6) + d] =
            __floats2half2_rn(o[di][0] * inv0, o[di][1] * inv0);
        *(__half2*)&g_A[((size_t)(b * SEQ_T + t1)) * D_EMB + (h << 6) + d] =
            __floats2half2_rn(o[di][2] * inv1, o[di][3] * inv1);
    }
}

// ---------------------------------------------------------------------------
extern "C" void kernel_launch(void* const* d_in, const int* in_sizes, int n_in,
                              void* d_out, int out_size) {
    const float* X  = (const float*)d_in[0];
    const float* Wq = (const float*)d_in[1];
    const float* Wk = (const float*)d_in[2];
    const float* Wv = (const float*)d_in[3];
    const float* Wo = (const float*)d_in[4];
    float* out = (float*)d_out;

    // 0) precision conversion (X -> half, W -> half transposed)
    cvt_x_kernel<<<(M_TOT * D_EMB) / (4 * 256), 256>>>(X);
    cvt_w_kernel<<<dim3(D_EMB / 32, D_EMB / 32, 4), 256>>>(Wq, Wk, Wv, Wo);

    // 1) QKV projections (z: 0=Q scaled, 1=K, 2=V transposed)
    gemm_h<0><<<dim3(D_EMB / 128, M_TOT / 128, 3), 256>>>(nullptr);

    // 2) causal flash attention
    attn_h<<<dim3(SEQ_T / 128, BATCH * NHEAD), 256>>>();

    // 3) output projection
    gemm_h<1><<<dim3(D_EMB / 128, M_TOT / 128), 256>>>(out);
}

// round 4
// speedup vs baseline: 6.9682x; 1.1223x over previous
#include <cuda_runtime.h>
#include <cuda_fp16.h>
#include <math.h>

#define D_EMB   1024
#define SEQ_T   2048
#define BATCH   2
#define NHEAD   16
#define DK      64
#define M_TOT   (BATCH * SEQ_T)

// ---------------- device scratch (allocation-free rule) ----------------
__device__ __half g_Xh[(size_t)M_TOT * D_EMB];              // X in half
__device__ __half g_Wt[4ULL * D_EMB * D_EMB];               // W^T half: [z][n][k]
__device__ __half g_Q[(size_t)BATCH * NHEAD * SEQ_T * DK];  // [B,H,T,Dk], pre-scaled by 0.125*log2e
__device__ __half g_K[(size_t)BATCH * NHEAD * SEQ_T * DK];  // [B,H,T,Dk]
__device__ __half g_V[(size_t)BATCH * NHEAD * DK * SEQ_T];  // [B,H,Dk,T] (transposed)
__device__ __half g_A[(size_t)M_TOT * D_EMB];               // [B,T,H*Dk]

// ---------------- helpers ----------------
__device__ __forceinline__ void cp16(void* dst, const void* src) {
    unsigned s = (unsigned)__cvta_generic_to_shared(dst);
    asm volatile("cp.async.cg.shared.global [%0], [%1], 16;" :: "r"(s), "l"(src));
}
__device__ __forceinline__ void cp_commit() { asm volatile("cp.async.commit_group;"); }
template <int N>
__device__ __forceinline__ void cp_wait() { asm volatile("cp.async.wait_group %0;" :: "n"(N)); }

__device__ __forceinline__ void ldsm4(unsigned r[4], const __half* p) {
    unsigned a = (unsigned)__cvta_generic_to_shared(p);
    asm volatile("ldmatrix.sync.aligned.m8n8.x4.shared.b16 {%0,%1,%2,%3}, [%4];"
                 : "=r"(r[0]), "=r"(r[1]), "=r"(r[2]), "=r"(r[3]) : "r"(a));
}

__device__ __forceinline__ void mma16(float* c, unsigned a0, unsigned a1, unsigned a2,
                                      unsigned a3, unsigned b0, unsigned b1) {
    asm volatile(
        "mma.sync.aligned.m16n8k16.row.col.f32.f16.f16.f32 "
        "{%0,%1,%2,%3},{%4,%5,%6,%7},{%8,%9},{%0,%1,%2,%3};\n"
        : "+f"(c[0]), "+f"(c[1]), "+f"(c[2]), "+f"(c[3])
        : "r"(a0), "r"(a1), "r"(a2), "r"(a3), "r"(b0), "r"(b1));
}
__device__ __forceinline__ unsigned h2u(float x, float y) {
    __half2 h = __floats2half2_rn(x, y);
    return *(unsigned*)&h;
}
__device__ __forceinline__ float ex2(float x) {
    float y; asm("ex2.approx.f32 %0, %1;" : "=f"(y) : "f"(x)); return y;
}

// ---------------- converters ----------------
__global__ void cvt_x_kernel(const float* __restrict__ X) {
    const int i = blockIdx.x * 256 + threadIdx.x;
    float4 v = ((const float4*)X)[i];
    __half2* d = (__half2*)g_Xh + (size_t)i * 2;
    d[0] = __floats2half2_rn(v.x, v.y);
    d[1] = __floats2half2_rn(v.z, v.w);
}

__global__ void cvt_w_kernel(const float* __restrict__ W0, const float* __restrict__ W1,
                             const float* __restrict__ W2, const float* __restrict__ W3) {
    __shared__ float Ws[32][33];
    const int z = blockIdx.z;
    const float* W = (z == 0) ? W0 : (z == 1) ? W1 : (z == 2) ? W2 : W3;
    __half* dst = g_Wt + (size_t)z * D_EMB * D_EMB;
    const int kb = blockIdx.y << 5;
    const int nb = blockIdx.x << 5;
    const int tid = threadIdx.x;
    {
        const int r = tid >> 3;
        const int c4 = (tid & 7) << 2;
        float4 v = *(const float4*)&W[(size_t)(kb + r) * D_EMB + nb + c4];
        Ws[r][c4 + 0] = v.x; Ws[r][c4 + 1] = v.y; Ws[r][c4 + 2] = v.z; Ws[r][c4 + 3] = v.w;
    }
    __syncthreads();
#pragma unroll
    for (int it = 0; it < 2; it++) {
        const int e = tid + it * 256;
        const int n = e >> 4;
        const int k2 = (e & 15) << 1;
        __half2 h = __floats2half2_rn(Ws[k2][n], Ws[k2 + 1][n]);
        *(__half2*)&dst[(size_t)(nb + n) * D_EMB + kb + k2] = h;
    }
}

// ---------------- fp16 GEMM: 128x128 tile, BK=32, 3-stage cp.async, ldmatrix ----
#define GSWZ(r, c) (((r) << 5) + ((((c) ^ (((r) >> 1) & 3))) << 3))
#define QSCALE 0.18033688011112042f   /* 0.125 * log2(e) */

template <int MODE>
__global__ __launch_bounds__(256, 2) void gemm_h(float* __restrict__ out) {
    __shared__ __align__(16) __half As[3][128 * 32];
    __shared__ __align__(16) __half Bs[3][128 * 32];

    const int tid  = threadIdx.x;
    const int lane = tid & 31;
    const int sel  = lane >> 3;
    const int l7   = lane & 7;
    const int wrp  = tid >> 5;
    const int wr   = wrp >> 2;
    const int wc   = wrp & 3;
    const int m0   = blockIdx.y << 7;
    const int n0   = blockIdx.x << 7;

    const __half* A  = (MODE == 0) ? g_Xh : g_A;
    const __half* Bw = g_Wt + (size_t)((MODE == 0) ? blockIdx.z : 3) * (D_EMB * D_EMB);

    const int lr = tid >> 1;           // 0..127
    const int lc = (tid & 1) << 1;     // chunk base 0 or 2
    const __half* Asrc = A + (size_t)(m0 + lr) * D_EMB;
    const __half* Bsrc = Bw + (size_t)(n0 + lr) * D_EMB;

    // ldmatrix per-lane constants
    const int xr     = (l7 >> 1) & 3;
    const int a_base = (wr * 64 + ((sel & 1) << 3) + l7) << 5;
    const int a_cb   = sel >> 1;
    const int b_base = (wc * 32 + ((sel >> 1) << 3) + l7) << 5;
    const int b_cb   = sel & 1;

    float acc[4][4][4];
#pragma unroll
    for (int mi = 0; mi < 4; mi++)
#pragma unroll
        for (int ni = 0; ni < 4; ni++)
#pragma unroll
            for (int c = 0; c < 4; c++) acc[mi][ni][c] = 0.0f;

    // prologue: stages 0,1
#pragma unroll
    for (int st = 0; st < 2; st++) {
        const size_t ko = (size_t)st * 32;
#pragma unroll
        for (int i = 0; i < 2; i++) {
            const int c = lc + i;
            cp16(&As[st][GSWZ(lr, c)], Asrc + ko + c * 8);
            cp16(&Bs[st][GSWZ(lr, c)], Bsrc + ko + c * 8);
        }
        cp_commit();
    }

    const int NK = D_EMB / 32;   // 32
    int cur = 0;
    for (int kt = 0; kt < NK; kt++) {
        if (kt + 2 < NK) {
            const int nb3 = (cur + 2 >= 3) ? cur - 1 : cur + 2;
            const size_t ko = (size_t)(kt + 2) * 32;
#pragma unroll
            for (int i = 0; i < 2; i++) {
                const int c = lc + i;
                cp16(&As[nb3][GSWZ(lr, c)], Asrc + ko + c * 8);
                cp16(&Bs[nb3][GSWZ(lr, c)], Bsrc + ko + c * 8);
            }
        }
        cp_commit();
        cp_wait<2>();
        __syncthreads();

#pragma unroll
        for (int kk = 0; kk < 2; kk++) {
            unsigned a[4][4];
#pragma unroll
            for (int mi = 0; mi < 4; mi++)
                ldsm4(a[mi], &As[cur][a_base + mi * 512 + (((2 * kk + a_cb) ^ xr) << 3)]);
#pragma unroll
            for (int p = 0; p < 2; p++) {
                unsigned bb[4];
                ldsm4(bb, &Bs[cur][b_base + p * 512 + (((2 * kk + b_cb) ^ xr) << 3)]);
#pragma unroll
                for (int mi = 0; mi < 4; mi++) {
                    mma16(acc[mi][2 * p],     a[mi][0], a[mi][1], a[mi][2], a[mi][3], bb[0], bb[1]);
                    mma16(acc[mi][2 * p + 1], a[mi][0], a[mi][1], a[mi][2], a[mi][3], bb[2], bb[3]);
                }
            }
        }
        __syncthreads();
        cur = (cur + 1 >= 3) ? 0 : cur + 1;
    }

    // epilogue
    const int g = lane >> 2;
    const int t = lane & 3;
#pragma unroll
    for (int mi = 0; mi < 4; mi++) {
        const int row0 = m0 + wr * 64 + mi * 16 + g;
#pragma unroll
        for (int ni = 0; ni < 4; ni++) {
            const int col = n0 + wc * 32 + ni * 8 + 2 * t;
            float c0 = acc[mi][ni][0], c1 = acc[mi][ni][1];
            float c2 = acc[mi][ni][2], c3 = acc[mi][ni][3];
            if (MODE == 0) {
                const int z = blockIdx.z;
                if (z == 0) { c0 *= QSCALE; c1 *= QSCALE; c2 *= QSCALE; c3 *= QSCALE; }
                const int h = col >> 6, d = col & 63;
                const int b0i = row0 >> 11, t0 = row0 & 2047;
                const int r1 = row0 + 8;
                const int b1i = r1 >> 11, t1 = r1 & 2047;
                const int bh0 = (b0i << 4) + h;
                const int bh1 = (b1i << 4) + h;
                if (z == 2) {   // V transposed: [B,H,Dk,T]
                    g_V[((size_t)bh0 * DK + d)     * SEQ_T + t0] = __float2half_rn(c0);
                    g_V[((size_t)bh0 * DK + d + 1) * SEQ_T + t0] = __float2half_rn(c1);
                    g_V[((size_t)bh1 * DK + d)     * SEQ_T + t1] = __float2half_rn(c2);
                    g_V[((size_t)bh1 * DK + d + 1) * SEQ_T + t1] = __float2half_rn(c3);
                } else {
                    __half* dst = (z == 0) ? g_Q : g_K;
                    *(__half2*)&dst[((size_t)bh0 * SEQ_T + t0) * DK + d] = __floats2half2_rn(c0, c1);
                    *(__half2*)&dst[((size_t)bh1 * SEQ_T + t1) * DK + d] = __floats2half2_rn(c2, c3);
                }
            } else {
                *(float2*)&out[(size_t)row0 * D_EMB + col]       = make_float2(c0, c1);
                *(float2*)&out[(size_t)(row0 + 8) * D_EMB + col] = make_float2(c2, c3);
            }
        }
    }
}

// ---------------- fp16 causal flash attention, ldmatrix + reg-resident Q/P ----
#define ASWZ(r, c) (((r) << 6) + ((((c) ^ ((r) & 7))) << 3))

__global__ __launch_bounds__(256, 2) void attn_h() {
    __shared__ __align__(16) __half Qs[128 * 64];
    __shared__ __align__(16) __half Ks[2][64 * 64];
    __shared__ __align__(16) __half Vs[2][64 * 64];

    const int tid  = threadIdx.x;
    const int lane = tid & 31;
    const int sel  = lane >> 3;
    const int l7   = lane & 7;
    const int g    = lane >> 2;
    const int t    = lane & 3;
    const int w    = tid >> 5;
    const int qt   = gridDim.x - 1 - blockIdx.x;   // heavy tiles first
    const int bh   = blockIdx.y;
    const int qbase = qt << 7;

    const __half* qg = g_Q + ((size_t)bh * SEQ_T + qbase) * DK;
    const __half* kg = g_K + (size_t)bh * SEQ_T * DK;
    const __half* vg = g_V + (size_t)bh * DK * SEQ_T;

    // ldmatrix per-lane constants (A-type for Q, B-type for K/V)
    const int q_base = (w * 16 + ((sel & 1) << 3) + l7) << 6;
    const int q_cb   = sel >> 1;
    const int kv_base = ((((sel >> 1) << 3) + l7)) << 6;
    const int kv_cb   = sel & 1;

    // prologue: group0 = Q tile, group1 = KV tile 0
    {
        const int r = tid >> 1;
        const int cb = (tid & 1) << 2;
#pragma unroll
        for (int i = 0; i < 4; i++) {
            const int c = cb + i;
            cp16(&Qs[ASWZ(r, c)], qg + (size_t)r * DK + c * 8);
        }
        cp_commit();
    }
    {
        const int r = tid >> 2;
        const int cb = (tid & 3) << 1;
#pragma unroll
        for (int i = 0; i < 2; i++) {
            const int c = cb + i;
            cp16(&Ks[0][ASWZ(r, c)], kg + (size_t)r * DK + c * 8);
            cp16(&Vs[0][ASWZ(r, c)], vg + (size_t)r * SEQ_T + c * 8);
        }
        cp_commit();
    }
    cp_wait<1>();
    __syncthreads();

    // Q fragments: registers for the whole kv loop
    unsigned q[4][4];
#pragma unroll
    for (int kk = 0; kk < 4; kk++)
        ldsm4(q[kk], &Qs[q_base + (((2 * kk + q_cb) ^ l7) << 3)]);

    float o[8][4];
#pragma unroll
    for (int di = 0; di < 8; di++)
#pragma unroll
        for (int c = 0; c < 4; c++) o[di][c] = 0.0f;
    float m0 = -1e30f, m1 = -1e30f, l0 = 0.0f, l1 = 0.0f;

    const int jmax = 2 * qt + 1;
    for (int j0 = 0; j0 <= jmax; j0++) {
        const int cur = j0 & 1;
        if (j0 < jmax) {
            const int nxt = cur ^ 1;
            const int r = tid >> 2;
            const int cb = (tid & 3) << 1;
#pragma unroll
            for (int i = 0; i < 2; i++) {
                const int c = cb + i;
                cp16(&Ks[nxt][ASWZ(r, c)], kg + (size_t)((j0 + 1) * 64 + r) * DK + c * 8);
                cp16(&Vs[nxt][ASWZ(r, c)], vg + (size_t)r * SEQ_T + (j0 + 1) * 64 + c * 8);
            }
        }
        cp_commit();
        cp_wait<1>();
        __syncthreads();

        // skip warp-tiles that are entirely above the causal diagonal
        const bool active = (64 * j0 <= qbase + w * 16 + 15);
        if (active) {
            // S = Q * K^T
            float s[8][4];
#pragma unroll
            for (int ni = 0; ni < 8; ni++)
#pragma unroll
                for (int c = 0; c < 4; c++) s[ni][c] = 0.0f;

#pragma unroll
            for (int kk = 0; kk < 4; kk++) {
#pragma unroll
                for (int p = 0; p < 4; p++) {
                    unsigned kb[4];
                    ldsm4(kb, &Ks[cur][kv_base + p * 1024 + (((2 * kk + kv_cb) ^ l7) << 3)]);
                    mma16(s[2 * p],     q[kk][0], q[kk][1], q[kk][2], q[kk][3], kb[0], kb[1]);
                    mma16(s[2 * p + 1], q[kk][0], q[kk][1], q[kk][2], q[kk][3], kb[2], kb[3]);
                }
            }

            // causal mask
            if (j0 >= 2 * qt) {
                const int r0g = qbase + w * 16 + g;
                const int r1g = r0g + 8;
                const int cb = j0 * 64 + 2 * t;
#pragma unroll
                for (int ni = 0; ni < 8; ni++) {
                    const int c0 = cb + ni * 8;
                    if (c0 > r0g)     s[ni][0] = -1e30f;
                    if (c0 + 1 > r0g) s[ni][1] = -1e30f;
                    if (c0 > r1g)     s[ni][2] = -1e30f;
                    if (c0 + 1 > r1g) s[ni][3] = -1e30f;
                }
            }

            // online softmax in base-2 domain (Q pre-scaled by log2e)
            float mx0 = -1e30f, mx1 = -1e30f;
#pragma unroll
            for (int ni = 0; ni < 8; ni++) {
                mx0 = fmaxf(mx0, fmaxf(s[ni][0], s[ni][1]));
                mx1 = fmaxf(mx1, fmaxf(s[ni][2], s[ni][3]));
            }
            mx0 = fmaxf(mx0, __shfl_xor_sync(0xffffffffu, mx0, 1));
            mx0 = fmaxf(mx0, __shfl_xor_sync(0xffffffffu, mx0, 2));
            mx1 = fmaxf(mx1, __shfl_xor_sync(0xffffffffu, mx1, 1));
            mx1 = fmaxf(mx1, __shfl_xor_sync(0xffffffffu, mx1, 2));

            const float mn0 = fmaxf(m0, mx0);
            const float mn1 = fmaxf(m1, mx1);
            const float al0 = ex2(m0 - mn0);
            const float al1 = ex2(m1 - mn1);
            float rs0 = 0.0f, rs1 = 0.0f;
#pragma unroll
            for (int ni = 0; ni < 8; ni++) {
                s[ni][0] = ex2(s[ni][0] - mn0); rs0 += s[ni][0];
                s[ni][1] = ex2(s[ni][1] - mn0); rs0 += s[ni][1];
                s[ni][2] = ex2(s[ni][2] - mn1); rs1 += s[ni][2];
                s[ni][3] = ex2(s[ni][3] - mn1); rs1 += s[ni][3];
            }
            rs0 += __shfl_xor_sync(0xffffffffu, rs0, 1);
            rs0 += __shfl_xor_sync(0xffffffffu, rs0, 2);
            rs1 += __shfl_xor_sync(0xffffffffu, rs1, 1);
            rs1 += __shfl_xor_sync(0xffffffffu, rs1, 2);
            l0 = l0 * al0 + rs0; m0 = mn0;
            l1 = l1 * al1 + rs1; m1 = mn1;
#pragma unroll
            for (int di = 0; di < 8; di++) {
                o[di][0] *= al0; o[di][1] *= al0;
                o[di][2] *= al1; o[di][3] *= al1;
            }

            // O += P * V (P repacked from S accumulators)
#pragma unroll
            for (int kk = 0; kk < 4; kk++) {
                const unsigned a0 = h2u(s[2 * kk][0],     s[2 * kk][1]);
                const unsigned a1 = h2u(s[2 * kk][2],     s[2 * kk][3]);
                const unsigned a2 = h2u(s[2 * kk + 1][0], s[2 * kk + 1][1]);
                const unsigned a3 = h2u(s[2 * kk + 1][2], s[2 * kk + 1][3]);
#pragma unroll
                for (int p = 0; p < 4; p++) {
                    unsigned vb[4];
                    ldsm4(vb, &Vs[cur][kv_base + p * 1024 + (((2 * kk + kv_cb) ^ l7) << 3)]);
                    mma16(o[2 * p],     a0, a1, a2, a3, vb[0], vb[1]);
                    mma16(o[2 * p + 1], a0, a1, a2, a3, vb[2], vb[3]);
                }
            }
        }
        __syncthreads();
    }

    // epilogue -> g_A [B,T,H*Dk] half
    const int b = bh >> 4;
    const int h = bh & 15;
    const float inv0 = 1.0f / l0;
    const float inv1 = 1.0f / l1;
    const int t0 = qbase + w * 16 + g;
    const int t1 = t0 + 8;
#pragma unroll
    for (int di = 0; di < 8; di++) {
        const int d = di * 8 + 2 * t;
        *(__half2*)&g_A[((size_t)(b * SEQ_T + t0)) * D_EMB + (h << 6) + d] =
            __floats2half2_rn(o[di][0] * inv0, o[di][1] * inv0);
        *(__half2*)&g_A[((size_t)(b * SEQ_T + t1)) * D_EMB + (h << 6) + d] =
            __floats2half2_rn(o[di][2] * inv1, o[di][3] * inv1);
    }
}

// ---------------------------------------------------------------------------
extern "C" void kernel_launch(void* const* d_in, const int* in_sizes, int n_in,
                              void* d_out, int out_size) {
    const float* X  = (const float*)d_in[0];
    const float* Wq = (const float*)d_in[1];
    const float* Wk = (const float*)d_in[2];
    const float* Wv = (const float*)d_in[3];
    const float* Wo = (const float*)d_in[4];
    float* out = (float*)d_out;

    // 0) precision conversion
    cvt_x_kernel<<<(M_TOT * D_EMB) / (4 * 256), 256>>>(X);
    cvt_w_kernel<<<dim3(D_EMB / 32, D_EMB / 32, 4), 256>>>(Wq, Wk, Wv, Wo);

    // 1) QKV projections (z: 0=Q scaled, 1=K, 2=V transposed)
    gemm_h<0><<<dim3(D_EMB / 128, M_TOT / 128, 3), 256>>>(nullptr);

    // 2) causal flash attention
    attn_h<<<dim3(SEQ_T / 128, BATCH * NHEAD), 256>>>();

    // 3) output projection
    gemm_h<1><<<dim3(D_EMB / 128, M_TOT / 128), 256>>>(out);
}